// round 1
// baseline (speedup 1.0000x reference)
#include <cuda_runtime.h>

#define BB 2048
#define SS 160
#define LL 128
#define DD 256
#define KK 16

#define THREADS 256
#define GROUPS 4            // rows processed per block iteration
#define B_PER_BLOCK 64
#define ITERS (B_PER_BLOCK / GROUPS)          // 16
#define NBLOCKS (LL * (BB / B_PER_BLOCK))     // 128 * 32 = 4096

__global__ __launch_bounds__(THREADS, 2)
void action_emb_kernel(const int*   __restrict__ token_ids,
                       const int*   __restrict__ actors,
                       const int*   __restrict__ streets,
                       const float* __restrict__ masks,
                       const float* __restrict__ actor_w,
                       const float* __restrict__ street_w,
                       const float* __restrict__ pos_w,
                       const float* __restrict__ mlp_w,
                       const float* __restrict__ mlp_b,
                       const float* __restrict__ ln_g,
                       const float* __restrict__ ln_b,
                       float*       __restrict__ out)
{
    const int tid  = threadIdx.x;
    const int g    = tid >> 6;        // row group within block: 0..3
    const int t2   = tid & 63;        // thread within row: 0..63
    const int d0   = t2 << 2;         // first of 4 owned d-columns
    const int lane = tid & 31;
    const int wing = (tid >> 5) & 1;  // warp index within the 64-thread row group

    const int l     = blockIdx.x & (LL - 1);
    const int chunk = blockIdx.x >> 7;
    const int b0    = chunk * B_PER_BLOCK + g;   // first b handled by this group

    // ---- per-thread constants (registers) ----
    float4 w[KK];
#pragma unroll
    for (int k = 0; k < KK; k++)
        w[k] = *(const float4*)(mlp_w + k * DD + d0);
    const float4 bias = *(const float4*)(mlp_b + d0);
    const float4 gn   = *(const float4*)(ln_g + d0);
    const float4 bn   = *(const float4*)(ln_b + d0);
    const float4 pos  = *(const float4*)(pos_w + l * DD + d0);

    __shared__ float red[2][GROUPS][2][2];  // [buf][group][warp][0=s,1=sq]

    // incremental pointers (group g starts at b = b0, advances by GROUPS rows)
    const float* mptr = masks + (b0 * SS + l) * KK;
    int          idc  = b0 * SS + l;
    int          oofs = (b0 * LL + l) * DD + d0;

    const int MSTEP = GROUPS * SS * KK;   // mask floats per iteration step
    const int ISTEP = GROUPS * SS;
    const int OSTEP = GROUPS * LL * DD;

#pragma unroll 1
    for (int it = 0; it < ITERS; it++) {
        // ---- broadcast loads for this group's row ----
        const float4 m0 = __ldg((const float4*)mptr + 0);
        const float4 m1 = __ldg((const float4*)mptr + 1);
        const float4 m2 = __ldg((const float4*)mptr + 2);
        const float4 m3 = __ldg((const float4*)mptr + 3);
        const int tok   = __ldg(token_ids + idc);
        const int aidx  = __ldg(actors    + idc);
        const int sidx  = __ldg(streets   + idc);

        // ---- h = masks @ mlp_w + mlp_b  (16 FMAs per owned d) ----
        float h0 = bias.x, h1 = bias.y, h2 = bias.z, h3 = bias.w;
        float mm[KK] = {m0.x, m0.y, m0.z, m0.w,
                        m1.x, m1.y, m1.z, m1.w,
                        m2.x, m2.y, m2.z, m2.w,
                        m3.x, m3.y, m3.z, m3.w};
#pragma unroll
        for (int k = 0; k < KK; k++) {
            h0 = fmaf(mm[k], w[k].x, h0);
            h1 = fmaf(mm[k], w[k].y, h1);
            h2 = fmaf(mm[k], w[k].z, h2);
            h3 = fmaf(mm[k], w[k].w, h3);
        }

        // ---- LayerNorm statistics over d (64 threads x 4 d = 256) ----
        float s  = (h0 + h1) + (h2 + h3);
        float sq = fmaf(h0, h0, fmaf(h1, h1, fmaf(h2, h2, h3 * h3)));
#pragma unroll
        for (int o = 16; o > 0; o >>= 1) {
            s  += __shfl_xor_sync(0xffffffffu, s,  o);
            sq += __shfl_xor_sync(0xffffffffu, sq, o);
        }
        const int buf = it & 1;
        if (lane == 0) {
            red[buf][g][wing][0] = s;
            red[buf][g][wing][1] = sq;
        }
        __syncthreads();
        const float st  = s  + red[buf][g][wing ^ 1][0];
        const float sqt = sq + red[buf][g][wing ^ 1][1];

        const float mu  = st * (1.0f / DD);
        const float var = fmaf(-mu, mu, sqt * (1.0f / DD));
        const float rs  = rsqrtf(var + 1e-5f);

        // ---- epilogue: LN affine, relu, embedding adds, validity ----
        const float4 aw = __ldg((const float4*)(actor_w  + aidx * DD + d0));
        const float4 sw = __ldg((const float4*)(street_w + sidx * DD + d0));

        float4 o;
        o.x = fmaxf(fmaf((h0 - mu) * rs, gn.x, bn.x), 0.0f) + aw.x + sw.x + pos.x;
        o.y = fmaxf(fmaf((h1 - mu) * rs, gn.y, bn.y), 0.0f) + aw.y + sw.y + pos.y;
        o.z = fmaxf(fmaf((h2 - mu) * rs, gn.z, bn.z), 0.0f) + aw.z + sw.z + pos.z;
        o.w = fmaxf(fmaf((h3 - mu) * rs, gn.w, bn.w), 0.0f) + aw.w + sw.w + pos.w;

        if (tok < 0) { o.x = 0.0f; o.y = 0.0f; o.z = 0.0f; o.w = 0.0f; }

        *(float4*)(out + oofs) = o;

        mptr += MSTEP;
        idc  += ISTEP;
        oofs += OSTEP;
    }
}

extern "C" void kernel_launch(void* const* d_in, const int* in_sizes, int n_in,
                              void* d_out, int out_size)
{
    const int*   token_ids = (const int*)  d_in[0];
    const int*   actors    = (const int*)  d_in[1];
    const int*   streets   = (const int*)  d_in[2];
    const float* masks     = (const float*)d_in[3];
    const float* actor_w   = (const float*)d_in[4];
    const float* street_w  = (const float*)d_in[5];
    const float* pos_w     = (const float*)d_in[6];
    const float* mlp_w     = (const float*)d_in[7];
    const float* mlp_b     = (const float*)d_in[8];
    const float* ln_g      = (const float*)d_in[9];
    const float* ln_b      = (const float*)d_in[10];
    float*       out       = (float*)d_out;

    action_emb_kernel<<<NBLOCKS, THREADS>>>(
        token_ids, actors, streets, masks,
        actor_w, street_w, pos_w, mlp_w, mlp_b, ln_g, ln_b, out);
}

// round 2
// speedup vs baseline: 1.3653x; 1.3653x over previous
#include <cuda_runtime.h>
#include <cstdint>

#define BB 2048
#define SS 160
#define LL 128
#define DD 256
#define KK 16

#define THREADS 256
#define GROUPS 4            // rows processed per block iteration
#define B_PER_BLOCK 64
#define ITERS (B_PER_BLOCK / GROUPS)          // 16
#define NBLOCKS (LL * (BB / B_PER_BLOCK))     // 128 * 32 = 4096
#define NSLOTS 4

struct __align__(16) Slot {
    float m[KK];        // 64 B of masks for one row
    int   tok, act, str, pad;
};

__device__ __forceinline__ uint32_t saddr(const void* p) {
    return (uint32_t)__cvta_generic_to_shared(p);
}
__device__ __forceinline__ void cp16(uint32_t s, const void* g) {
    asm volatile("cp.async.cg.shared.global [%0], [%1], 16;" :: "r"(s), "l"(g));
}
__device__ __forceinline__ void cp4(uint32_t s, const void* g) {
    asm volatile("cp.async.ca.shared.global [%0], [%1], 4;" :: "r"(s), "l"(g));
}
#define CP_COMMIT() asm volatile("cp.async.commit_group;" ::: "memory")
#define CP_WAIT1()  asm volatile("cp.async.wait_group 1;" ::: "memory")

__global__ __launch_bounds__(THREADS, 2)
void action_emb_kernel(const int*   __restrict__ token_ids,
                       const int*   __restrict__ actors,
                       const int*   __restrict__ streets,
                       const float* __restrict__ masks,
                       const float* __restrict__ actor_w,
                       const float* __restrict__ street_w,
                       const float* __restrict__ pos_w,
                       const float* __restrict__ mlp_w,
                       const float* __restrict__ mlp_b,
                       const float* __restrict__ ln_g,
                       const float* __restrict__ ln_b,
                       float*       __restrict__ out)
{
    const int tid  = threadIdx.x;
    const int g    = tid >> 6;        // row group within block: 0..3
    const int t2   = tid & 63;        // thread within row: 0..63
    const int d0   = t2 << 2;         // first of 4 owned d-columns
    const int lane = tid & 31;
    const int wing = (tid >> 5) & 1;  // warp within the 64-thread group

    const int l     = blockIdx.x & (LL - 1);
    const int chunk = blockIdx.x >> 7;
    const int b0    = chunk * B_PER_BLOCK + g;   // first b for this group

    __shared__ Slot  slots[NSLOTS][GROUPS];
    __shared__ float red[2][GROUPS][2][2];       // [buf][group][warp][s,sq]

    // ---- per-thread constants (registers) ----
    float4 w[KK];
#pragma unroll
    for (int k = 0; k < KK; k++)
        w[k] = *(const float4*)(mlp_w + k * DD + d0);
    const float4 bias = *(const float4*)(mlp_b + d0);
    const float4 gn   = *(const float4*)(ln_g + d0);
    const float4 bn   = *(const float4*)(ln_b + d0);
    const float4 pos  = *(const float4*)(pos_w + l * DD + d0);

    int oofs = (b0 * LL + l) * DD + d0;
    const int OSTEP = GROUPS * LL * DD;

    // ---- prefetch issue helper (producers: t2 in [0,7)) ----
    auto issue = [&](int it2) {
        if (it2 < ITERS) {
            const int b   = b0 + it2 * GROUPS;
            const int idc = b * SS + l;
            Slot* sl = &slots[it2 & (NSLOTS - 1)][g];
            if (t2 < 4)       cp16(saddr(&sl->m[t2 * 4]), masks + (size_t)idc * KK + t2 * 4);
            else if (t2 == 4) cp4(saddr(&sl->tok), token_ids + idc);
            else if (t2 == 5) cp4(saddr(&sl->act), actors + idc);
            else if (t2 == 6) cp4(saddr(&sl->str), streets + idc);
        }
        CP_COMMIT();   // all threads commit (possibly empty) -> uniform group count
    };

    // prologue: fill slots 0 and 1
    issue(0);
    issue(1);
    CP_WAIT1();        // slot 0 landed
    __syncthreads();   // publish to the whole block

#pragma unroll 1
    for (int it = 0; it < ITERS; it++) {
        Slot* sl = &slots[it & (NSLOTS - 1)][g];

        // ---- ids first: launch the gather loads ASAP ----
        const int tok  = sl->tok;
        const int aidx = sl->act;
        const int sidx = sl->str;
        const float4 aw = __ldg((const float4*)(actor_w  + aidx * DD + d0));
        const float4 sw = __ldg((const float4*)(street_w + sidx * DD + d0));

        const float4 m0 = *(const float4*)&sl->m[0];
        const float4 m1 = *(const float4*)&sl->m[4];
        const float4 m2 = *(const float4*)&sl->m[8];
        const float4 m3 = *(const float4*)&sl->m[12];

        // ---- h = masks @ mlp_w + mlp_b ----
        float h0 = bias.x, h1 = bias.y, h2 = bias.z, h3 = bias.w;
        const float mm[KK] = {m0.x, m0.y, m0.z, m0.w,
                              m1.x, m1.y, m1.z, m1.w,
                              m2.x, m2.y, m2.z, m2.w,
                              m3.x, m3.y, m3.z, m3.w};
#pragma unroll
        for (int k = 0; k < KK; k++) {
            h0 = fmaf(mm[k], w[k].x, h0);
            h1 = fmaf(mm[k], w[k].y, h1);
            h2 = fmaf(mm[k], w[k].z, h2);
            h3 = fmaf(mm[k], w[k].w, h3);
        }

        // ---- LN statistics ----
        float s  = (h0 + h1) + (h2 + h3);
        float sq = fmaf(h0, h0, fmaf(h1, h1, fmaf(h2, h2, h3 * h3)));
#pragma unroll
        for (int o = 16; o > 0; o >>= 1) {
            s  += __shfl_xor_sync(0xffffffffu, s,  o);
            sq += __shfl_xor_sync(0xffffffffu, sq, o);
        }
        const int buf = it & 1;
        if (lane == 0) {
            red[buf][g][wing][0] = s;
            red[buf][g][wing][1] = sq;
        }

        // ---- prefetch two iterations ahead, then group-local barrier ----
        issue(it + 2);
        CP_WAIT1();                          // all but newest group done -> slot it+1 ready
        asm volatile("bar.sync %0, 64;" :: "r"(g + 1) : "memory");

        const float st  = s  + red[buf][g][wing ^ 1][0];
        const float sqt = sq + red[buf][g][wing ^ 1][1];

        const float mu  = st * (1.0f / DD);
        const float var = fmaf(-mu, mu, sqt * (1.0f / DD));
        const float rs  = rsqrtf(var + 1e-5f);

        // ---- epilogue ----
        float4 o;
        o.x = fmaxf(fmaf((h0 - mu) * rs, gn.x, bn.x), 0.0f) + aw.x + sw.x + pos.x;
        o.y = fmaxf(fmaf((h1 - mu) * rs, gn.y, bn.y), 0.0f) + aw.y + sw.y + pos.y;
        o.z = fmaxf(fmaf((h2 - mu) * rs, gn.z, bn.z), 0.0f) + aw.z + sw.z + pos.z;
        o.w = fmaxf(fmaf((h3 - mu) * rs, gn.w, bn.w), 0.0f) + aw.w + sw.w + pos.w;

        if (tok < 0) { o.x = 0.0f; o.y = 0.0f; o.z = 0.0f; o.w = 0.0f; }

        *(float4*)(out + oofs) = o;
        oofs += OSTEP;
    }
}

extern "C" void kernel_launch(void* const* d_in, const int* in_sizes, int n_in,
                              void* d_out, int out_size)
{
    const int*   token_ids = (const int*)  d_in[0];
    const int*   actors    = (const int*)  d_in[1];
    const int*   streets   = (const int*)  d_in[2];
    const float* masks     = (const float*)d_in[3];
    const float* actor_w   = (const float*)d_in[4];
    const float* street_w  = (const float*)d_in[5];
    const float* pos_w     = (const float*)d_in[6];
    const float* mlp_w     = (const float*)d_in[7];
    const float* mlp_b     = (const float*)d_in[8];
    const float* ln_g      = (const float*)d_in[9];
    const float* ln_b      = (const float*)d_in[10];
    float*       out       = (float*)d_out;

    action_emb_kernel<<<NBLOCKS, THREADS>>>(
        token_ids, actors, streets, masks,
        actor_w, street_w, pos_w, mlp_w, mlp_b, ln_g, ln_b, out);
}